// round 8
// baseline (speedup 1.0000x reference)
#include <cuda_runtime.h>

// LSTM: B=4096, T=512, I=10, H=32, O=1. Gate order i,f,g,o.
// R8: R2's exact schedule (k-inner interleaved fma2, recurrent weights in
// registers as f32x2 j-pairs, even/odd-j halves in u64 halves, x-weights in
// smem) with NB=3 batches/warp -> 1366 single-warp blocks, ONE wave at
// 10 blocks/SM (launch_bounds(32,10), ~195 regs). +33% warps/SMSP vs R2.

#define B_TOT 4096
#define T_LEN 512
#define I_DIM 10
#define H_DIM 32
#define NB 3
#define NPX 5
#define GRID ((B_TOT + NB - 1) / NB)   // 1366

typedef unsigned long long u64;

__device__ __forceinline__ u64 fma2(u64 a, u64 b, u64 c) {
    u64 d;
    asm("fma.rn.f32x2 %0, %1, %2, %3;" : "=l"(d) : "l"(a), "l"(b), "l"(c));
    return d;
}
__device__ __forceinline__ u64 pack2(float lo, float hi) {
    u64 d;
    asm("mov.b64 %0, {%1, %2};" : "=l"(d) : "f"(lo), "f"(hi));
    return d;
}
__device__ __forceinline__ void unpack2(u64 v, float& lo, float& hi) {
    asm("mov.b64 {%0, %1}, %2;" : "=f"(lo), "=f"(hi) : "l"(v));
}
__device__ __forceinline__ float ex2f(float x) {
    float y; asm("ex2.approx.f32 %0, %1;" : "=f"(y) : "f"(x)); return y;
}
__device__ __forceinline__ float rcpf(float x) {
    float y; asm("rcp.approx.f32 %0, %1;" : "=f"(y) : "f"(x)); return y;
}
__device__ __forceinline__ float sigf(float x) {
    return rcpf(1.0f + ex2f(-1.4426950408889634f * x));
}
__device__ __forceinline__ float tanh_f(float x) {
    return fmaf(2.0f, rcpf(1.0f + ex2f(-2.8853900817779268f * x)), -1.0f);
}

__global__ __launch_bounds__(32, 10) void lstm_r8_kernel(
    const float* __restrict__ x,    // [B, T, I]
    const float* __restrict__ Wih,  // [4H, I]
    const float* __restrict__ Whh,  // [4H, H]
    const float* __restrict__ bih,  // [4H]
    const float* __restrict__ bhh,  // [4H]
    const float* __restrict__ Wd,   // [1, H]
    const float* __restrict__ bd,   // [1]
    float* __restrict__ out)        // [B, 1]
{
    __shared__ ulonglong2 sWx_if[NPX][32];   // 2.5 KB
    __shared__ ulonglong2 sWx_go[NPX][32];   // 2.5 KB
    __shared__ __align__(16) float sH[NB][H_DIM];
    __shared__ __align__(16) float sX[NB][12];

    const int lane = threadIdx.x;
    const int b0 = blockIdx.x * NB;

    // ---- Recurrent weights into registers (paired over j) ----
    u64 whi[16], whf[16], whg[16], who[16];
#pragma unroll
    for (int p = 0; p < 16; p++) {
        whi[p] = *(const u64*)&Whh[(0 * 32 + lane) * H_DIM + 2 * p];
        whf[p] = *(const u64*)&Whh[(1 * 32 + lane) * H_DIM + 2 * p];
        whg[p] = *(const u64*)&Whh[(2 * 32 + lane) * H_DIM + 2 * p];
        who[p] = *(const u64*)&Whh[(3 * 32 + lane) * H_DIM + 2 * p];
    }
    // x-weights into smem, packed per gate-pair.
#pragma unroll
    for (int p = 0; p < NPX; p++) {
        ulonglong2 v;
        v.x = pack2(Wih[(0 * 32 + lane) * I_DIM + 2 * p], Wih[(0 * 32 + lane) * I_DIM + 2 * p + 1]);
        v.y = pack2(Wih[(1 * 32 + lane) * I_DIM + 2 * p], Wih[(1 * 32 + lane) * I_DIM + 2 * p + 1]);
        sWx_if[p][lane] = v;
        v.x = pack2(Wih[(2 * 32 + lane) * I_DIM + 2 * p], Wih[(2 * 32 + lane) * I_DIM + 2 * p + 1]);
        v.y = pack2(Wih[(3 * 32 + lane) * I_DIM + 2 * p], Wih[(3 * 32 + lane) * I_DIM + 2 * p + 1]);
        sWx_go[p][lane] = v;
    }
    // Bias folded into accumulator init: (bias, 0); preact = lo + hi.
    const u64 bp_i = pack2(bih[0 * 32 + lane] + bhh[0 * 32 + lane], 0.0f);
    const u64 bp_f = pack2(bih[1 * 32 + lane] + bhh[1 * 32 + lane], 0.0f);
    const u64 bp_g = pack2(bih[2 * 32 + lane] + bhh[2 * 32 + lane], 0.0f);
    const u64 bp_o = pack2(bih[3 * 32 + lane] + bhh[3 * 32 + lane], 0.0f);
    __syncwarp();

    float h[NB], c[NB], xv[NB];
    const float* xp[NB];
#pragma unroll
    for (int k = 0; k < NB; k++) {
        h[k] = 0.0f; c[k] = 0.0f; xv[k] = 0.0f;
        const int bk = (b0 + k < B_TOT) ? (b0 + k) : (B_TOT - 1);  // tail clamp
        xp[k] = x + (bk * T_LEN) * I_DIM + lane;
    }
    if (lane < I_DIM) {
#pragma unroll
        for (int k = 0; k < NB; k++) xv[k] = *xp[k];
    }

    for (int t = 0; t < T_LEN; t++) {
        // Publish compact h and x.
#pragma unroll
        for (int k = 0; k < NB; k++) sH[k][lane] = h[k];
        if (lane < I_DIM) {
#pragma unroll
            for (int k = 0; k < NB; k++) sX[k][lane] = xv[k];
        }
        __syncwarp();

        // Prefetch next timestep's x (overlaps gate compute below).
        if (t + 1 < T_LEN) {
            if (lane < I_DIM) {
#pragma unroll
                for (int k = 0; k < NB; k++) { xp[k] += I_DIM; xv[k] = *xp[k]; }
            }
        }

        // Accumulators: lo half = even-j sum (+bias), hi half = odd-j sum.
        u64 ai[NB], af[NB], ag[NB], ao[NB];
#pragma unroll
        for (int k = 0; k < NB; k++) { ai[k] = bp_i; af[k] = bp_f; ag[k] = bp_g; ao[k] = bp_o; }

        // Recurrent part: q-outer, k-inner (12 independent fma2 chains).
#pragma unroll
        for (int q = 0; q < 8; q++) {
#pragma unroll
            for (int k = 0; k < NB; k++) {
                const ulonglong2 hp = *(const ulonglong2*)&sH[k][4 * q];
                ai[k] = fma2(whi[2 * q],     hp.x, ai[k]);
                af[k] = fma2(whf[2 * q],     hp.x, af[k]);
                ag[k] = fma2(whg[2 * q],     hp.x, ag[k]);
                ao[k] = fma2(who[2 * q],     hp.x, ao[k]);
                ai[k] = fma2(whi[2 * q + 1], hp.y, ai[k]);
                af[k] = fma2(whf[2 * q + 1], hp.y, af[k]);
                ag[k] = fma2(whg[2 * q + 1], hp.y, ag[k]);
                ao[k] = fma2(who[2 * q + 1], hp.y, ao[k]);
            }
        }
        // Input part: p-outer so only 4 weight u64s live at a time.
#pragma unroll
        for (int p = 0; p < NPX; p++) {
            const ulonglong2 wif = sWx_if[p][lane];
            const ulonglong2 wgo = sWx_go[p][lane];
#pragma unroll
            for (int k = 0; k < NB; k++) {
                const u64 xq = *(const u64*)&sX[k][2 * p];
                ai[k] = fma2(wif.x, xq, ai[k]);
                af[k] = fma2(wif.y, xq, af[k]);
                ag[k] = fma2(wgo.x, xq, ag[k]);
                ao[k] = fma2(wgo.y, xq, ao[k]);
            }
        }

        // Activations + state update.
#pragma unroll
        for (int k = 0; k < NB; k++) {
            float lo, hi;
            unpack2(ai[k], lo, hi); const float gi = sigf(lo + hi);
            unpack2(af[k], lo, hi); const float gf = sigf(lo + hi);
            unpack2(ag[k], lo, hi); const float gg = tanh_f(lo + hi);
            unpack2(ao[k], lo, hi); const float go = sigf(lo + hi);
            c[k] = fmaf(gf, c[k], gi * gg);
            h[k] = go * tanh_f(c[k]);
        }
        __syncwarp();
    }

    // Final dense: out[b] = sum_l h[b][l] * Wd[l] + bd (store tail-guarded).
    const float wd = Wd[lane];
    const float bdv = bd[0];
#pragma unroll
    for (int k = 0; k < NB; k++) {
        float p = h[k] * wd;
#pragma unroll
        for (int off = 16; off; off >>= 1)
            p += __shfl_xor_sync(0xffffffffu, p, off);
        if (lane == 0 && b0 + k < B_TOT) out[b0 + k] = p + bdv;
    }
}

extern "C" void kernel_launch(void* const* d_in, const int* in_sizes, int n_in,
                              void* d_out, int out_size) {
    const float* x   = (const float*)d_in[0];
    const float* Wih = (const float*)d_in[1];
    const float* Whh = (const float*)d_in[2];
    const float* bih = (const float*)d_in[3];
    const float* bhh = (const float*)d_in[4];
    const float* Wd  = (const float*)d_in[5];
    const float* bd  = (const float*)d_in[6];
    (void)in_sizes; (void)n_in; (void)out_size;

    lstm_r8_kernel<<<GRID, 32>>>(x, Wih, Whh, bih, bhh, Wd, bd,
                                 (float*)d_out);
}

// round 9
// speedup vs baseline: 1.9296x; 1.9296x over previous
#include <cuda_runtime.h>

// LSTM: B=4096, T=512, I=10, H=32, O=1. Gate order i,f,g,o.
// R9 = R2 (NB=4 batches/warp, recurrent weights in regs as f32x2 j-pairs,
// even/odd-j halves in u64 halves, k-inner interleaved schedule) plus:
//  - x-part of step t+1 software-pipelined into step t's MUFU shadow
//  - manual x2 t-unroll with LITERAL ping-pong parity (all smem addrs static)
//  - one __syncwarp per step (ping-pong removes the second)
//  - bias peeled into first x-part fma2 (no acc-init MOVs)
//  - weights pre-scaled by -log2e (i,f,o) / -2log2e (g): activations need no mul
// One wave: 1024 single-warp blocks, 7/SM bound.

#define B_TOT 4096
#define T_LEN 512
#define I_DIM 10
#define H_DIM 32
#define NB 4
#define XSTRIDE (T_LEN * I_DIM)   // 5120

#define S1 (-1.4426950408889634f)  // -log2(e): sigmoid gates i, f, o
#define S2 (-2.8853900817779268f)  // -2*log2(e): tanh gate g

typedef unsigned long long u64;

__device__ __forceinline__ u64 fma2(u64 a, u64 b, u64 c) {
    u64 d;
    asm("fma.rn.f32x2 %0, %1, %2, %3;" : "=l"(d) : "l"(a), "l"(b), "l"(c));
    return d;
}
__device__ __forceinline__ u64 pack2(float lo, float hi) {
    u64 d;
    asm("mov.b64 %0, {%1, %2};" : "=l"(d) : "f"(lo), "f"(hi));
    return d;
}
__device__ __forceinline__ void unpack2(u64 v, float& lo, float& hi) {
    asm("mov.b64 {%0, %1}, %2;" : "=f"(lo), "=f"(hi) : "l"(v));
}
__device__ __forceinline__ float ex2f(float x) {
    float y; asm("ex2.approx.f32 %0, %1;" : "=f"(y) : "f"(x)); return y;
}
__device__ __forceinline__ float rcpf(float x) {
    float y; asm("rcp.approx.f32 %0, %1;" : "=f"(y) : "f"(x)); return y;
}
// Pre-scaled activations: y already = -log2e*x (sig) or -2log2e*x (tanh).
__device__ __forceinline__ float sig_pre(float y) {
    return rcpf(1.0f + ex2f(y));
}
__device__ __forceinline__ float tanh_pre(float y) {
    return fmaf(2.0f, rcpf(1.0f + ex2f(y)), -1.0f);
}
// Full tanh for c (not pre-scalable).
__device__ __forceinline__ float tanh_c(float x) {
    return fmaf(2.0f, rcpf(1.0f + ex2f(S2 * x)), -1.0f);
}

__global__ __launch_bounds__(32, 7) void lstm_r9_kernel(
    const float* __restrict__ x,    // [B, T, I]
    const float* __restrict__ Wih,  // [4H, I]
    const float* __restrict__ Whh,  // [4H, H]
    const float* __restrict__ bih,  // [4H]
    const float* __restrict__ bhh,  // [4H]
    const float* __restrict__ Wd,   // [1, H]
    const float* __restrict__ bd,   // [1]
    float* __restrict__ out)        // [B, 1]
{
    __shared__ ulonglong2 sWx_if[5][32];             // pre-scaled x-weights
    __shared__ ulonglong2 sWx_go[5][32];
    __shared__ __align__(16) float sH[2][NB][H_DIM]; // ping-pong
    __shared__ __align__(16) float sX[2][NB][12];    // ping-pong, 48B rows

    const int lane = threadIdx.x;
    const int b0 = blockIdx.x * NB;

    // ---- Recurrent weights into registers, PRE-SCALED (paired over j) ----
    u64 whi[16], whf[16], whg[16], who[16];
#pragma unroll
    for (int p = 0; p < 16; p++) {
        const float* r0 = &Whh[(0 * 32 + lane) * H_DIM + 2 * p];
        const float* r1 = &Whh[(1 * 32 + lane) * H_DIM + 2 * p];
        const float* r2 = &Whh[(2 * 32 + lane) * H_DIM + 2 * p];
        const float* r3 = &Whh[(3 * 32 + lane) * H_DIM + 2 * p];
        whi[p] = pack2(S1 * r0[0], S1 * r0[1]);
        whf[p] = pack2(S1 * r1[0], S1 * r1[1]);
        whg[p] = pack2(S2 * r2[0], S2 * r2[1]);
        who[p] = pack2(S1 * r3[0], S1 * r3[1]);
    }
    // x-weights into smem, pre-scaled, packed per gate-pair.
#pragma unroll
    for (int p = 0; p < 5; p++) {
        ulonglong2 v;
        v.x = pack2(S1 * Wih[(0 * 32 + lane) * I_DIM + 2 * p],
                    S1 * Wih[(0 * 32 + lane) * I_DIM + 2 * p + 1]);
        v.y = pack2(S1 * Wih[(1 * 32 + lane) * I_DIM + 2 * p],
                    S1 * Wih[(1 * 32 + lane) * I_DIM + 2 * p + 1]);
        sWx_if[p][lane] = v;
        v.x = pack2(S2 * Wih[(2 * 32 + lane) * I_DIM + 2 * p],
                    S2 * Wih[(2 * 32 + lane) * I_DIM + 2 * p + 1]);
        v.y = pack2(S1 * Wih[(3 * 32 + lane) * I_DIM + 2 * p],
                    S1 * Wih[(3 * 32 + lane) * I_DIM + 2 * p + 1]);
        sWx_go[p][lane] = v;
    }
    // Pre-scaled bias, packed (bias, 0) for the peeled fma2.
    const u64 bp_i = pack2(S1 * (bih[0 * 32 + lane] + bhh[0 * 32 + lane]), 0.0f);
    const u64 bp_f = pack2(S1 * (bih[1 * 32 + lane] + bhh[1 * 32 + lane]), 0.0f);
    const u64 bp_g = pack2(S2 * (bih[2 * 32 + lane] + bhh[2 * 32 + lane]), 0.0f);
    const u64 bp_o = pack2(S1 * (bih[3 * 32 + lane] + bhh[3 * 32 + lane]), 0.0f);

    float h[NB], c[NB], xv[NB];
#pragma unroll
    for (int k = 0; k < NB; k++) { h[k] = 0.0f; c[k] = 0.0f; xv[k] = 0.0f; }

    const float* xb = x + b0 * XSTRIDE + lane;

    // ---- Prologue: x(0) -> sX[1] (scratch); accs = bias + Wx*x(0); xv = x(1)
    if (lane < I_DIM) {
#pragma unroll
        for (int k = 0; k < NB; k++) sX[1][k][lane] = xb[k * XSTRIDE];
    }
    __syncwarp();
    u64 ai[NB], af[NB], ag[NB], ao[NB];
    {
        const ulonglong2 wif0 = sWx_if[0][lane];
        const ulonglong2 wgo0 = sWx_go[0][lane];
#pragma unroll
        for (int k = 0; k < NB; k++) {
            const u64 xq = *(const u64*)&sX[1][k][0];
            ai[k] = fma2(wif0.x, xq, bp_i);
            af[k] = fma2(wif0.y, xq, bp_f);
            ag[k] = fma2(wgo0.x, xq, bp_g);
            ao[k] = fma2(wgo0.y, xq, bp_o);
        }
#pragma unroll
        for (int p = 1; p < 5; p++) {
            const ulonglong2 wif = sWx_if[p][lane];
            const ulonglong2 wgo = sWx_go[p][lane];
#pragma unroll
            for (int k = 0; k < NB; k++) {
                const u64 xq = *(const u64*)&sX[1][k][2 * p];
                ai[k] = fma2(wif.x, xq, ai[k]);
                af[k] = fma2(wif.y, xq, af[k]);
                ag[k] = fma2(wgo.x, xq, ag[k]);
                ao[k] = fma2(wgo.y, xq, ao[k]);
            }
        }
    }
    if (lane < I_DIM) {
#pragma unroll
        for (int k = 0; k < NB; k++) xv[k] = xb[k * XSTRIDE + I_DIM];  // x(1)
    }
    int toff = 2 * I_DIM;   // element offset of x(t+2), clamped later

    // ---- Step body macro: parity A is a LITERAL (static smem addressing) ----
#define STEP_BODY(A)                                                          \
    {                                                                         \
        /* 1. publish h(t) and x(t+1) into buffer A */                        \
        _Pragma("unroll")                                                     \
        for (int k = 0; k < NB; k++) sH[A][k][lane] = h[k];                   \
        if (lane < I_DIM) {                                                   \
            _Pragma("unroll")                                                 \
            for (int k = 0; k < NB; k++) sX[A][k][lane] = xv[k];              \
        }                                                                     \
        __syncwarp();                                                         \
        /* 2. LDG x(t+2) (clamped), long latency hidden across the step */    \
        if (lane < I_DIM) {                                                   \
            _Pragma("unroll")                                                 \
            for (int k = 0; k < NB; k++) xv[k] = xb[k * XSTRIDE + toff];      \
        }                                                                     \
        toff = min(toff + I_DIM, XSTRIDE - I_DIM);                            \
        /* 3. recurrent: accs += Whh*h(t)  (accs held bias + x(t) part) */    \
        _Pragma("unroll")                                                     \
        for (int q = 0; q < 8; q++) {                                         \
            _Pragma("unroll")                                                 \
            for (int k = 0; k < NB; k++) {                                    \
                const ulonglong2 hp = *(const ulonglong2*)&sH[A][k][4 * q];   \
                ai[k] = fma2(whi[2 * q],     hp.x, ai[k]);                    \
                af[k] = fma2(whf[2 * q],     hp.x, af[k]);                    \
                ag[k] = fma2(whg[2 * q],     hp.x, ag[k]);                    \
                ao[k] = fma2(who[2 * q],     hp.x, ao[k]);                    \
                ai[k] = fma2(whi[2 * q + 1], hp.y, ai[k]);                    \
                af[k] = fma2(whf[2 * q + 1], hp.y, af[k]);                    \
                ag[k] = fma2(whg[2 * q + 1], hp.y, ag[k]);                    \
                ao[k] = fma2(who[2 * q + 1], hp.y, ao[k]);                    \
            }                                                                 \
        }                                                                     \
        /* 4. preacts = lo + hi */                                            \
        float pi[NB], pf[NB], pg[NB], po[NB];                                 \
        _Pragma("unroll")                                                     \
        for (int k = 0; k < NB; k++) {                                        \
            float lo, hi;                                                     \
            unpack2(ai[k], lo, hi); pi[k] = lo + hi;                          \
            unpack2(af[k], lo, hi); pf[k] = lo + hi;                          \
            unpack2(ag[k], lo, hi); pg[k] = lo + hi;                          \
            unpack2(ao[k], lo, hi); po[k] = lo + hi;                          \
        }                                                                     \
        /* 5. x-part for t+1 into fresh accs (bias peeled) — fills MUFU shadow */ \
        {                                                                     \
            const ulonglong2 wif0 = sWx_if[0][lane];                          \
            const ulonglong2 wgo0 = sWx_go[0][lane];                          \
            _Pragma("unroll")                                                 \
            for (int k = 0; k < NB; k++) {                                    \
                const u64 xq = *(const u64*)&sX[A][k][0];                     \
                ai[k] = fma2(wif0.x, xq, bp_i);                               \
                af[k] = fma2(wif0.y, xq, bp_f);                               \
                ag[k] = fma2(wgo0.x, xq, bp_g);                               \
                ao[k] = fma2(wgo0.y, xq, bp_o);                               \
            }                                                                 \
            _Pragma("unroll")                                                 \
            for (int p = 1; p < 5; p++) {                                     \
                const ulonglong2 wif = sWx_if[p][lane];                       \
                const ulonglong2 wgo = sWx_go[p][lane];                       \
                _Pragma("unroll")                                             \
                for (int k = 0; k < NB; k++) {                                \
                    const u64 xq = *(const u64*)&sX[A][k][2 * p];             \
                    ai[k] = fma2(wif.x, xq, ai[k]);                           \
                    af[k] = fma2(wif.y, xq, af[k]);                           \
                    ag[k] = fma2(wgo.x, xq, ag[k]);                           \
                    ao[k] = fma2(wgo.y, xq, ao[k]);                           \
                }                                                             \
            }                                                                 \
        }                                                                     \
        /* 6. activations + state update (pre-scaled forms) */                \
        _Pragma("unroll")                                                     \
        for (int k = 0; k < NB; k++) {                                        \
            const float gi = sig_pre(pi[k]);                                  \
            const float gf = sig_pre(pf[k]);                                  \
            const float gg = tanh_pre(pg[k]);                                 \
            const float go = sig_pre(po[k]);                                  \
            c[k] = fmaf(gf, c[k], gi * gg);                                   \
            h[k] = go * tanh_c(c[k]);                                         \
        }                                                                     \
    }

#pragma unroll 1
    for (int t = 0; t < T_LEN; t += 2) {
        STEP_BODY(0)
        STEP_BODY(1)
    }
#undef STEP_BODY

    // ---- Final dense: out[b] = sum_l h[b][l] * Wd[l] + bd ----
    const float wd = Wd[lane];
    const float bdv = bd[0];
#pragma unroll
    for (int k = 0; k < NB; k++) {
        float p = h[k] * wd;
#pragma unroll
        for (int off = 16; off; off >>= 1)
            p += __shfl_xor_sync(0xffffffffu, p, off);
        if (lane == 0) out[b0 + k] = p + bdv;
    }
}

extern "C" void kernel_launch(void* const* d_in, const int* in_sizes, int n_in,
                              void* d_out, int out_size) {
    const float* x   = (const float*)d_in[0];
    const float* Wih = (const float*)d_in[1];
    const float* Whh = (const float*)d_in[2];
    const float* bih = (const float*)d_in[3];
    const float* bhh = (const float*)d_in[4];
    const float* Wd  = (const float*)d_in[5];
    const float* bd  = (const float*)d_in[6];
    (void)in_sizes; (void)n_in; (void)out_size;

    lstm_r9_kernel<<<B_TOT / NB, 32>>>(x, Wih, Whh, bih, bhh, Wd, bd,
                                       (float*)d_out);
}

// round 10
// speedup vs baseline: 1.9974x; 1.0351x over previous
#include <cuda_runtime.h>

// LSTM: B=4096, T=512, I=10, H=32, O=1. Gate order i,f,g,o.
// R10 = R2's exact schedule (recurrent weights in regs as f32x2 j-pairs,
// even/odd-j halves accumulate in u64 halves, k-inner interleave, x-weights
// in smem, two __syncwarp/step) with:
//  - MIXED grid: 544 blocks x NB=4 + 640 blocks x NB=3 = 1184 = 148*8 blocks
//    -> exactly one wave at 8 blocks/SM (2.0 warps/SMSP vs R2's 1.73).
//  - weights/bias pre-scaled by -log2e (sig) / -2log2e (tanh): no activation muls
//  - bias peeled into the q=0 fma2: no accumulator-init MOVs

#define B_TOT 4096
#define T_LEN 512
#define I_DIM 10
#define H_DIM 32
#define XSTRIDE (T_LEN * I_DIM)   // 5120
#define NB4_BLOCKS 544
#define NB3_BLOCKS 640
#define GRID_SZ (NB4_BLOCKS + NB3_BLOCKS)   // 1184 = 148*8

#define S1 (-1.4426950408889634f)  // -log2(e): sigmoid gates i, f, o
#define S2 (-2.8853900817779268f)  // -2*log2(e): tanh gate g

typedef unsigned long long u64;

__device__ __forceinline__ u64 fma2(u64 a, u64 b, u64 c) {
    u64 d;
    asm("fma.rn.f32x2 %0, %1, %2, %3;" : "=l"(d) : "l"(a), "l"(b), "l"(c));
    return d;
}
__device__ __forceinline__ u64 pack2(float lo, float hi) {
    u64 d;
    asm("mov.b64 %0, {%1, %2};" : "=l"(d) : "f"(lo), "f"(hi));
    return d;
}
__device__ __forceinline__ void unpack2(u64 v, float& lo, float& hi) {
    asm("mov.b64 {%0, %1}, %2;" : "=f"(lo), "=f"(hi) : "l"(v));
}
__device__ __forceinline__ float ex2f(float x) {
    float y; asm("ex2.approx.f32 %0, %1;" : "=f"(y) : "f"(x)); return y;
}
__device__ __forceinline__ float rcpf(float x) {
    float y; asm("rcp.approx.f32 %0, %1;" : "=f"(y) : "f"(x)); return y;
}
// Pre-scaled activations: input already multiplied by S1 (sig) / S2 (tanh).
__device__ __forceinline__ float sig_pre(float y) {
    return rcpf(1.0f + ex2f(y));
}
__device__ __forceinline__ float tanh_pre(float y) {
    return fmaf(2.0f, rcpf(1.0f + ex2f(y)), -1.0f);
}
__device__ __forceinline__ float tanh_c(float x) {   // normal-domain tanh
    return fmaf(2.0f, rcpf(1.0f + ex2f(S2 * x)), -1.0f);
}

template<int NBk>
__device__ __forceinline__ void lstm_run(
    int lane, int b0,
    const u64 (&whi)[16], const u64 (&whf)[16],
    const u64 (&whg)[16], const u64 (&who)[16],
    u64 bp_i, u64 bp_f, u64 bp_g, u64 bp_o,
    const ulonglong2 (*sWx_if)[32], const ulonglong2 (*sWx_go)[32],
    float (*sH)[H_DIM], float (*sX)[12],
    const float* __restrict__ x,
    const float* __restrict__ Wd, const float* __restrict__ bd,
    float* __restrict__ out)
{
    float h[NBk], c[NBk], xv[NBk];
#pragma unroll
    for (int k = 0; k < NBk; k++) { h[k] = 0.0f; c[k] = 0.0f; xv[k] = 0.0f; }

    const float* xb = x + b0 * XSTRIDE + lane;
    if (lane < I_DIM) {
#pragma unroll
        for (int k = 0; k < NBk; k++) xv[k] = xb[k * XSTRIDE];   // x(0)
    }
    int toff = I_DIM;   // element offset of x(t+1)

    for (int t = 0; t < T_LEN; t++) {
        // Publish compact h and x.
#pragma unroll
        for (int k = 0; k < NBk; k++) sH[k][lane] = h[k];
        if (lane < I_DIM) {
#pragma unroll
            for (int k = 0; k < NBk; k++) sX[k][lane] = xv[k];
        }
        __syncwarp();

        // Prefetch next timestep's x (clamped; overlaps gate compute).
        if (lane < I_DIM) {
#pragma unroll
            for (int k = 0; k < NBk; k++) xv[k] = xb[k * XSTRIDE + toff];
        }
        toff = min(toff + I_DIM, XSTRIDE - I_DIM);

        u64 ai[NBk], af[NBk], ag[NBk], ao[NBk];
        // q = 0 peeled: bias enters via the fma2 addend (no init MOVs).
#pragma unroll
        for (int k = 0; k < NBk; k++) {
            const ulonglong2 hp = *(const ulonglong2*)&sH[k][0];
            ai[k] = fma2(whi[0], hp.x, bp_i);
            af[k] = fma2(whf[0], hp.x, bp_f);
            ag[k] = fma2(whg[0], hp.x, bp_g);
            ao[k] = fma2(who[0], hp.x, bp_o);
            ai[k] = fma2(whi[1], hp.y, ai[k]);
            af[k] = fma2(whf[1], hp.y, af[k]);
            ag[k] = fma2(whg[1], hp.y, ag[k]);
            ao[k] = fma2(who[1], hp.y, ao[k]);
        }
#pragma unroll
        for (int q = 1; q < 8; q++) {
#pragma unroll
            for (int k = 0; k < NBk; k++) {
                const ulonglong2 hp = *(const ulonglong2*)&sH[k][4 * q];
                ai[k] = fma2(whi[2 * q],     hp.x, ai[k]);
                af[k] = fma2(whf[2 * q],     hp.x, af[k]);
                ag[k] = fma2(whg[2 * q],     hp.x, ag[k]);
                ao[k] = fma2(who[2 * q],     hp.x, ao[k]);
                ai[k] = fma2(whi[2 * q + 1], hp.y, ai[k]);
                af[k] = fma2(whf[2 * q + 1], hp.y, af[k]);
                ag[k] = fma2(whg[2 * q + 1], hp.y, ag[k]);
                ao[k] = fma2(who[2 * q + 1], hp.y, ao[k]);
            }
        }
        // Input part: p-outer so only 4 weight u64s live at a time.
#pragma unroll
        for (int p = 0; p < 5; p++) {
            const ulonglong2 wif = sWx_if[p][lane];
            const ulonglong2 wgo = sWx_go[p][lane];
#pragma unroll
            for (int k = 0; k < NBk; k++) {
                const u64 xq = *(const u64*)&sX[k][2 * p];
                ai[k] = fma2(wif.x, xq, ai[k]);
                af[k] = fma2(wif.y, xq, af[k]);
                ag[k] = fma2(wgo.x, xq, ag[k]);
                ao[k] = fma2(wgo.y, xq, ao[k]);
            }
        }

        // Activations (pre-scaled forms) + state update.
#pragma unroll
        for (int k = 0; k < NBk; k++) {
            float lo, hi;
            unpack2(ai[k], lo, hi); const float gi = sig_pre(lo + hi);
            unpack2(af[k], lo, hi); const float gf = sig_pre(lo + hi);
            unpack2(ag[k], lo, hi); const float gg = tanh_pre(lo + hi);
            unpack2(ao[k], lo, hi); const float go = sig_pre(lo + hi);
            c[k] = fmaf(gf, c[k], gi * gg);
            h[k] = go * tanh_c(c[k]);
        }
        __syncwarp();
    }

    // Final dense: out[b] = sum_l h[b][l] * Wd[l] + bd
    const float wd = Wd[lane];
    const float bdv = bd[0];
#pragma unroll
    for (int k = 0; k < NBk; k++) {
        float p = h[k] * wd;
#pragma unroll
        for (int off = 16; off; off >>= 1)
            p += __shfl_xor_sync(0xffffffffu, p, off);
        if (lane == 0) out[b0 + k] = p + bdv;
    }
}

__global__ __launch_bounds__(32, 8) void lstm_r10_kernel(
    const float* __restrict__ x,    // [B, T, I]
    const float* __restrict__ Wih,  // [4H, I]
    const float* __restrict__ Whh,  // [4H, H]
    const float* __restrict__ bih,  // [4H]
    const float* __restrict__ bhh,  // [4H]
    const float* __restrict__ Wd,   // [1, H]
    const float* __restrict__ bd,   // [1]
    float* __restrict__ out)        // [B, 1]
{
    __shared__ ulonglong2 sWx_if[5][32];   // pre-scaled x-weights
    __shared__ ulonglong2 sWx_go[5][32];
    __shared__ __align__(16) float sH[4][H_DIM];
    __shared__ __align__(16) float sX[4][12];

    const int lane = threadIdx.x;
    const int bid = blockIdx.x;

    // ---- Recurrent weights into registers, PRE-SCALED (paired over j) ----
    u64 whi[16], whf[16], whg[16], who[16];
#pragma unroll
    for (int p = 0; p < 16; p++) {
        const float* r0 = &Whh[(0 * 32 + lane) * H_DIM + 2 * p];
        const float* r1 = &Whh[(1 * 32 + lane) * H_DIM + 2 * p];
        const float* r2 = &Whh[(2 * 32 + lane) * H_DIM + 2 * p];
        const float* r3 = &Whh[(3 * 32 + lane) * H_DIM + 2 * p];
        whi[p] = pack2(S1 * r0[0], S1 * r0[1]);
        whf[p] = pack2(S1 * r1[0], S1 * r1[1]);
        whg[p] = pack2(S2 * r2[0], S2 * r2[1]);
        who[p] = pack2(S1 * r3[0], S1 * r3[1]);
    }
    // x-weights into smem, pre-scaled, packed per gate-pair.
#pragma unroll
    for (int p = 0; p < 5; p++) {
        ulonglong2 v;
        v.x = pack2(S1 * Wih[(0 * 32 + lane) * I_DIM + 2 * p],
                    S1 * Wih[(0 * 32 + lane) * I_DIM + 2 * p + 1]);
        v.y = pack2(S1 * Wih[(1 * 32 + lane) * I_DIM + 2 * p],
                    S1 * Wih[(1 * 32 + lane) * I_DIM + 2 * p + 1]);
        sWx_if[p][lane] = v;
        v.x = pack2(S2 * Wih[(2 * 32 + lane) * I_DIM + 2 * p],
                    S2 * Wih[(2 * 32 + lane) * I_DIM + 2 * p + 1]);
        v.y = pack2(S1 * Wih[(3 * 32 + lane) * I_DIM + 2 * p],
                    S1 * Wih[(3 * 32 + lane) * I_DIM + 2 * p + 1]);
        sWx_go[p][lane] = v;
    }
    // Pre-scaled bias packed (bias, 0) for the q=0 peeled fma2.
    const u64 bp_i = pack2(S1 * (bih[0 * 32 + lane] + bhh[0 * 32 + lane]), 0.0f);
    const u64 bp_f = pack2(S1 * (bih[1 * 32 + lane] + bhh[1 * 32 + lane]), 0.0f);
    const u64 bp_g = pack2(S2 * (bih[2 * 32 + lane] + bhh[2 * 32 + lane]), 0.0f);
    const u64 bp_o = pack2(S1 * (bih[3 * 32 + lane] + bhh[3 * 32 + lane]), 0.0f);
    __syncwarp();

    if (bid < NB4_BLOCKS) {
        lstm_run<4>(lane, 4 * bid,
                    whi, whf, whg, who, bp_i, bp_f, bp_g, bp_o,
                    sWx_if, sWx_go, sH, sX, x, Wd, bd, out);
    } else {
        lstm_run<3>(lane, NB4_BLOCKS * 4 + 3 * (bid - NB4_BLOCKS),
                    whi, whf, whg, who, bp_i, bp_f, bp_g, bp_o,
                    sWx_if, sWx_go, sH, sX, x, Wd, bd, out);
    }
}

extern "C" void kernel_launch(void* const* d_in, const int* in_sizes, int n_in,
                              void* d_out, int out_size) {
    const float* x   = (const float*)d_in[0];
    const float* Wih = (const float*)d_in[1];
    const float* Whh = (const float*)d_in[2];
    const float* bih = (const float*)d_in[3];
    const float* bhh = (const float*)d_in[4];
    const float* Wd  = (const float*)d_in[5];
    const float* bd  = (const float*)d_in[6];
    (void)in_sizes; (void)n_in; (void)out_size;

    lstm_r10_kernel<<<GRID_SZ, 32>>>(x, Wih, Whh, bih, bhh, Wd, bd,
                                     (float*)d_out);
}

// round 11
// speedup vs baseline: 2.0091x; 1.0058x over previous
#include <cuda_runtime.h>

// LSTM: B=4096, T=512, I=10, H=32, O=1. Gate order i,f,g,o.
// R11 = R10 algebra (recurrent weights in regs as PRE-SCALED f32x2 j-pairs,
// even/odd-j halves in u64 halves, k-inner interleave, bias peeled into q=0,
// x-weights in smem) on a uniform NB=4 / 1024-block grid, PLUS phase
// staggering: co-resident blocks (bid and bid+148 share an SM) get a one-time
// dependent-FMA delay of ~r*373 cyc (r = bid/148) so their per-step
// fma-dead activation windows interleave instead of phase-locking.

#define B_TOT 4096
#define T_LEN 512
#define I_DIM 10
#define H_DIM 32
#define NB 4
#define XSTRIDE (T_LEN * I_DIM)   // 5120

#define S1 (-1.4426950408889634f)  // -log2(e): sigmoid gates i, f, o
#define S2 (-2.8853900817779268f)  // -2*log2(e): tanh gate g

typedef unsigned long long u64;

__device__ __forceinline__ u64 fma2(u64 a, u64 b, u64 c) {
    u64 d;
    asm("fma.rn.f32x2 %0, %1, %2, %3;" : "=l"(d) : "l"(a), "l"(b), "l"(c));
    return d;
}
__device__ __forceinline__ u64 pack2(float lo, float hi) {
    u64 d;
    asm("mov.b64 %0, {%1, %2};" : "=l"(d) : "f"(lo), "f"(hi));
    return d;
}
__device__ __forceinline__ void unpack2(u64 v, float& lo, float& hi) {
    asm("mov.b64 {%0, %1}, %2;" : "=f"(lo), "=f"(hi) : "l"(v));
}
__device__ __forceinline__ float ex2f(float x) {
    float y; asm("ex2.approx.f32 %0, %1;" : "=f"(y) : "f"(x)); return y;
}
__device__ __forceinline__ float rcpf(float x) {
    float y; asm("rcp.approx.f32 %0, %1;" : "=f"(y) : "f"(x)); return y;
}
// Pre-scaled activations: input already multiplied by S1 (sig) / S2 (tanh).
__device__ __forceinline__ float sig_pre(float y) {
    return rcpf(1.0f + ex2f(y));
}
__device__ __forceinline__ float tanh_pre(float y) {
    return fmaf(2.0f, rcpf(1.0f + ex2f(y)), -1.0f);
}
__device__ __forceinline__ float tanh_c(float x) {   // normal-domain tanh
    return fmaf(2.0f, rcpf(1.0f + ex2f(S2 * x)), -1.0f);
}

__global__ __launch_bounds__(32, 7) void lstm_r11_kernel(
    const float* __restrict__ x,    // [B, T, I]
    const float* __restrict__ Wih,  // [4H, I]
    const float* __restrict__ Whh,  // [4H, H]
    const float* __restrict__ bih,  // [4H]
    const float* __restrict__ bhh,  // [4H]
    const float* __restrict__ Wd,   // [1, H]
    const float* __restrict__ bd,   // [1]
    float* __restrict__ out)        // [B, 1]
{
    __shared__ ulonglong2 sWx_if[5][32];   // pre-scaled x-weights
    __shared__ ulonglong2 sWx_go[5][32];
    __shared__ __align__(16) float sH[NB][H_DIM];
    __shared__ __align__(16) float sX[NB][12];    // cols 10,11 are padding

    const int lane = threadIdx.x;
    const int b0 = blockIdx.x * NB;

    // ---- Recurrent weights into registers, PRE-SCALED (paired over j) ----
    u64 whi[16], whf[16], whg[16], who[16];
#pragma unroll
    for (int p = 0; p < 16; p++) {
        const float* r0 = &Whh[(0 * 32 + lane) * H_DIM + 2 * p];
        const float* r1 = &Whh[(1 * 32 + lane) * H_DIM + 2 * p];
        const float* r2 = &Whh[(2 * 32 + lane) * H_DIM + 2 * p];
        const float* r3 = &Whh[(3 * 32 + lane) * H_DIM + 2 * p];
        whi[p] = pack2(S1 * r0[0], S1 * r0[1]);
        whf[p] = pack2(S1 * r1[0], S1 * r1[1]);
        whg[p] = pack2(S2 * r2[0], S2 * r2[1]);
        who[p] = pack2(S1 * r3[0], S1 * r3[1]);
    }
    // x-weights into smem, pre-scaled, packed per gate-pair.
#pragma unroll
    for (int p = 0; p < 5; p++) {
        ulonglong2 v;
        v.x = pack2(S1 * Wih[(0 * 32 + lane) * I_DIM + 2 * p],
                    S1 * Wih[(0 * 32 + lane) * I_DIM + 2 * p + 1]);
        v.y = pack2(S1 * Wih[(1 * 32 + lane) * I_DIM + 2 * p],
                    S1 * Wih[(1 * 32 + lane) * I_DIM + 2 * p + 1]);
        sWx_if[p][lane] = v;
        v.x = pack2(S2 * Wih[(2 * 32 + lane) * I_DIM + 2 * p],
                    S2 * Wih[(2 * 32 + lane) * I_DIM + 2 * p + 1]);
        v.y = pack2(S1 * Wih[(3 * 32 + lane) * I_DIM + 2 * p],
                    S1 * Wih[(3 * 32 + lane) * I_DIM + 2 * p + 1]);
        sWx_go[p][lane] = v;
    }
    // Pre-scaled bias packed (bias, 0) for the q=0 peeled fma2.
    const u64 bp_i = pack2(S1 * (bih[0 * 32 + lane] + bhh[0 * 32 + lane]), 0.0f);
    const u64 bp_f = pack2(S1 * (bih[1 * 32 + lane] + bhh[1 * 32 + lane]), 0.0f);
    const u64 bp_g = pack2(S2 * (bih[2 * 32 + lane] + bhh[2 * 32 + lane]), 0.0f);
    const u64 bp_o = pack2(S1 * (bih[3 * 32 + lane] + bhh[3 * 32 + lane]), 0.0f);

    // ---- Phase stagger: blocks bid and bid+148 co-reside on one SM.
    // Delay round r = bid/148 by ~r*373 cyc via a dependent fma chain whose
    // result lands in a dead smem padding slot (not elidable, never read).
    {
        const int round = blockIdx.x / 148;     // 0..6
        const int iters = round * 93;           // ~93 fma x 4 cyc = 372 cyc
        float j = 0.5f;
#pragma unroll 1
        for (int i = 0; i < iters; i++) j = fmaf(j, 0.9999f, 1e-4f);
        if (lane == 0) sX[0][11] = j;           // dead padding slot
    }
    __syncwarp();

    float h[NB], c[NB], xv[NB];
#pragma unroll
    for (int k = 0; k < NB; k++) { h[k] = 0.0f; c[k] = 0.0f; xv[k] = 0.0f; }

    const float* xb = x + b0 * XSTRIDE + lane;
    if (lane < I_DIM) {
#pragma unroll
        for (int k = 0; k < NB; k++) xv[k] = xb[k * XSTRIDE];   // x(0)
    }
    int toff = I_DIM;   // element offset of x(t+1)

    for (int t = 0; t < T_LEN; t++) {
        // Publish compact h and x.
#pragma unroll
        for (int k = 0; k < NB; k++) sH[k][lane] = h[k];
        if (lane < I_DIM) {
#pragma unroll
            for (int k = 0; k < NB; k++) sX[k][lane] = xv[k];
        }
        __syncwarp();

        // Prefetch next timestep's x (clamped; overlaps gate compute).
        if (lane < I_DIM) {
#pragma unroll
            for (int k = 0; k < NB; k++) xv[k] = xb[k * XSTRIDE + toff];
        }
        toff = min(toff + I_DIM, XSTRIDE - I_DIM);

        u64 ai[NB], af[NB], ag[NB], ao[NB];
        // q = 0 peeled: bias enters via the fma2 addend (no init MOVs).
#pragma unroll
        for (int k = 0; k < NB; k++) {
            const ulonglong2 hp = *(const ulonglong2*)&sH[k][0];
            ai[k] = fma2(whi[0], hp.x, bp_i);
            af[k] = fma2(whf[0], hp.x, bp_f);
            ag[k] = fma2(whg[0], hp.x, bp_g);
            ao[k] = fma2(who[0], hp.x, bp_o);
            ai[k] = fma2(whi[1], hp.y, ai[k]);
            af[k] = fma2(whf[1], hp.y, af[k]);
            ag[k] = fma2(whg[1], hp.y, ag[k]);
            ao[k] = fma2(who[1], hp.y, ao[k]);
        }
#pragma unroll
        for (int q = 1; q < 8; q++) {
#pragma unroll
            for (int k = 0; k < NB; k++) {
                const ulonglong2 hp = *(const ulonglong2*)&sH[k][4 * q];
                ai[k] = fma2(whi[2 * q],     hp.x, ai[k]);
                af[k] = fma2(whf[2 * q],     hp.x, af[k]);
                ag[k] = fma2(whg[2 * q],     hp.x, ag[k]);
                ao[k] = fma2(who[2 * q],     hp.x, ao[k]);
                ai[k] = fma2(whi[2 * q + 1], hp.y, ai[k]);
                af[k] = fma2(whf[2 * q + 1], hp.y, af[k]);
                ag[k] = fma2(whg[2 * q + 1], hp.y, ag[k]);
                ao[k] = fma2(who[2 * q + 1], hp.y, ao[k]);
            }
        }
        // Input part: p-outer so only 4 weight u64s live at a time.
#pragma unroll
        for (int p = 0; p < 5; p++) {
            const ulonglong2 wif = sWx_if[p][lane];
            const ulonglong2 wgo = sWx_go[p][lane];
#pragma unroll
            for (int k = 0; k < NB; k++) {
                const u64 xq = *(const u64*)&sX[k][2 * p];
                ai[k] = fma2(wif.x, xq, ai[k]);
                af[k] = fma2(wif.y, xq, af[k]);
                ag[k] = fma2(wgo.x, xq, ag[k]);
                ao[k] = fma2(wgo.y, xq, ao[k]);
            }
        }

        // Activations (pre-scaled forms) + state update.
#pragma unroll
        for (int k = 0; k < NB; k++) {
            float lo, hi;
            unpack2(ai[k], lo, hi); const float gi = sig_pre(lo + hi);
            unpack2(af[k], lo, hi); const float gf = sig_pre(lo + hi);
            unpack2(ag[k], lo, hi); const float gg = tanh_pre(lo + hi);
            unpack2(ao[k], lo, hi); const float go = sig_pre(lo + hi);
            c[k] = fmaf(gf, c[k], gi * gg);
            h[k] = go * tanh_c(c[k]);
        }
        __syncwarp();
    }

    // Final dense: out[b] = sum_l h[b][l] * Wd[l] + bd
    const float wd = Wd[lane];
    const float bdv = bd[0];
#pragma unroll
    for (int k = 0; k < NB; k++) {
        float p = h[k] * wd;
#pragma unroll
        for (int off = 16; off; off >>= 1)
            p += __shfl_xor_sync(0xffffffffu, p, off);
        if (lane == 0) out[b0 + k] = p + bdv;
    }
}

extern "C" void kernel_launch(void* const* d_in, const int* in_sizes, int n_in,
                              void* d_out, int out_size) {
    const float* x   = (const float*)d_in[0];
    const float* Wih = (const float*)d_in[1];
    const float* Whh = (const float*)d_in[2];
    const float* bih = (const float*)d_in[3];
    const float* bhh = (const float*)d_in[4];
    const float* Wd  = (const float*)d_in[5];
    const float* bd  = (const float*)d_in[6];
    (void)in_sizes; (void)n_in; (void)out_size;

    lstm_r11_kernel<<<B_TOT / NB, 32>>>(x, Wih, Whh, bih, bhh, Wd, bd,
                                        (float*)d_out);
}